// round 10
// baseline (speedup 1.0000x reference)
#include <cuda_runtime.h>

// FINAL (locked): out[i] = 2 * in[i], N = 100 floats (25 float4).
// Launch-latency-bound: ~3.4 us stable in-kernel fixed overhead plus a
// 1.1-2.0 us jittering graph-dispatch gap dominate; the 800 B of traffic
// is <0.2% of wall time. Eight profiled rounds covered every in-body axis
// (warps, vector width, math pipe, predication, thread count, store
// policy); all deltas were inside the +-0.5 us jitter band. This config
// holds the best observation (4.544 us) and the minimal SASS body:
// IMAD(addr) -> LDG.128 -> 4x FMUL -> STG.128 -> EXIT.
// - 25 threads: HW lane-masks the partial warp, zero predication.
// - st.global.cs streaming store: skip L2-allocate bookkeeping.
// - load default-cached: input stays L2-resident across graph replays.
__global__ void __launch_bounds__(32, 1) mul2_kernel(const float4* __restrict__ in,
                                                     float4* __restrict__ out) {
    int i = threadIdx.x;           // 0..24
    float4 v = __ldg(&in[i]);
    v.x *= 2.0f; v.y *= 2.0f; v.z *= 2.0f; v.w *= 2.0f;
    asm volatile("st.global.cs.v4.f32 [%0], {%1, %2, %3, %4};"
                 :: "l"(&out[i]), "f"(v.x), "f"(v.y), "f"(v.z), "f"(v.w)
                 : "memory");
}

extern "C" void kernel_launch(void* const* d_in, const int* in_sizes, int n_in,
                              void* d_out, int out_size) {
    const float4* in = (const float4*)d_in[0];
    float4* out = (float4*)d_out;
    mul2_kernel<<<1, 25>>>(in, out);
}

// round 11
// speedup vs baseline: 1.2000x; 1.2000x over previous
#include <cuda_runtime.h>

// out[i] = 2 * in[i], N = 100 floats (25 float4). Launch-latency-bound.
// Clean A/B vs the inline-asm streaming-store variant: plain C++ body,
// no asm, no "memory" clobber — ptxas emits the native minimal sequence
// LDG.E.128.CONSTANT -> 4x FMUL -> STG.E.128 with optimal stall/hold
// encoding. L1D is flushed per launch on sm_103a so cache hints on the
// load never mattered; L2 residency (default policy) is preserved.
// 25 threads: HW lane-masks the partial warp, zero predication.
__global__ void __launch_bounds__(32, 1) mul2_kernel(const float4* __restrict__ in,
                                                     float4* __restrict__ out) {
    int i = threadIdx.x;           // 0..24
    float4 v = in[i];
    v.x *= 2.0f; v.y *= 2.0f; v.z *= 2.0f; v.w *= 2.0f;
    out[i] = v;
}

extern "C" void kernel_launch(void* const* d_in, const int* in_sizes, int n_in,
                              void* d_out, int out_size) {
    const float4* in = (const float4*)d_in[0];
    float4* out = (float4*)d_out;
    mul2_kernel<<<1, 25>>>(in, out);
}

// round 12
// speedup vs baseline: 1.2083x; 1.0069x over previous
#include <cuda_runtime.h>

// FINAL: out[i] = 2 * in[i], N = 100 floats (25 float4).
// Launch-latency-bound: ~3.5 us stable in-kernel fixed overhead plus
// ~1.0-2.0 us harness graph-dispatch jitter dominate; the 800 B of data
// traffic is <0.2% of wall time. Ten profiled rounds exhausted every
// in-body axis (warp count, vector width, thread count, predication,
// math pipe, load path, store policy); all deltas were inside the
// +-0.5 us jitter band. Plain C++ body beat the inline-asm streaming
// store A/B (4.64 vs 5.1-5.6 us) and has the minimal SASS:
// LDG.E.128.CONSTANT -> 4x FMUL -> STG.E.128 -> EXIT.
// 25 threads: HW lane-masks the partial warp, zero predication.
__global__ void __launch_bounds__(32, 1) mul2_kernel(const float4* __restrict__ in,
                                                     float4* __restrict__ out) {
    int i = threadIdx.x;           // 0..24
    float4 v = in[i];
    v.x *= 2.0f; v.y *= 2.0f; v.z *= 2.0f; v.w *= 2.0f;
    out[i] = v;
}

extern "C" void kernel_launch(void* const* d_in, const int* in_sizes, int n_in,
                              void* d_out, int out_size) {
    const float4* in = (const float4*)d_in[0];
    float4* out = (float4*)d_out;
    mul2_kernel<<<1, 25>>>(in, out);
}